// round 8
// baseline (speedup 1.0000x reference)
#include <cuda_runtime.h>
#include <cuda_fp16.h>
#include <cstdint>

// ---------------- problem constants ----------------
#define M_TOTAL   14400      // 16 * 30 * 30
#define N_TOTAL   512
#define K_TOTAL   1152
#define OHW       900        // 30*30
#define XSTRIDE_N 262144     // 256*32*32
#define OSTRIDE_N 460800     // 512*900

#define BM 128
#define BN 64
#define BK 32
#define NCHUNK   36          // K_TOTAL / BK
#define MTILES   113         // ceil(14400/128)
#define NBLKS    8           // N_TOTAL / BN
#define NTHREADS 128
#define STAGES   4

// fp16 fragment-ordered tiles per chunk:
//   A (chunk,bm):  128x32 half = 8 KB = 512 uint4
//   B (chunk,bn):   32x64 half = 4 KB = 256 uint4
#define STAGE_A_BYTES 8192
#define STG_BYTES     12288
#define SM_TOTAL      (STAGES * STG_BYTES)    // 49152 B -> 4 CTAs/SM

__device__ uint4 g_ah[NCHUNK * MTILES * 512];   // ~33.3 MB
__device__ uint4 g_bh[NCHUNK * NBLKS * 256];    // ~1.2 MB

// ---------------- helpers ----------------
__device__ __forceinline__ uint32_t smem_u32(const void* p) {
    uint32_t a;
    asm("{ .reg .u64 t; cvta.to.shared.u64 t, %1; cvt.u32.u64 %0, t; }"
        : "=r"(a) : "l"(p));
    return a;
}
__device__ __forceinline__ void cp16(uint32_t dst, const void* src) {
    asm volatile("cp.async.cg.shared.global [%0], [%1], 16;"
                 :: "r"(dst), "l"(src) : "memory");
}
// pack two floats into f16x2 word: lo = a, hi = b
__device__ __forceinline__ uint32_t h2(float a, float b) {
    uint32_t r;
    asm("cvt.rn.f16x2.f32 %0, %1, %2;" : "=r"(r) : "f"(b), "f"(a));
    return r;
}

// ---------------- prep A: gathered im2col, fp16, fragment order ----------------
// block = one (chunk c, mtile bmt). Tile = 512 fragments (uint4), fragment
// fi = (((ks*2+slab)*4+mt)*32+lane); words a0..a3 of m16n8k16:
//   a0={A[m0][k0],A[m0][k0+1]} a1={A[m1][..]} a2={A[m0][k0+8],[k0+9]} a3={A[m1][..]}
//   m0 = slab*64+mt*16+gid, m1 = m0+8, k0 = ks*16 + 2*tig (within chunk)
__global__ void prep_a_kernel(const float* __restrict__ x,
                              const int*   __restrict__ idx) {
    __shared__ int skoff[BK];
    __shared__ int smb[BM];
    const int c   = blockIdx.x;
    const int bmt = blockIdx.y;
    const int t   = threadIdx.x;

    if (t < BK) {
        int v  = idx[c * BK + t];
        int ch = v / 9;
        int rs = v - ch * 9;
        skoff[t] = ch * 1024 + (rs / 3) * 32 + (rs % 3);
    }
    if (t < BM) {
        int m = bmt * BM + t;
        if (m >= M_TOTAL) m = 0;
        int nb  = m / OHW;
        int rem = m - nb * OHW;
        smb[t] = nb * XSTRIDE_N + (rem / 30) * 32 + (rem % 30);
    }
    __syncthreads();

    uint4* dst = g_ah + (size_t)(c * MTILES + bmt) * 512;
    #pragma unroll
    for (int fi = t; fi < 512; fi += NTHREADS) {
        int lane = fi & 31;
        int mt   = (fi >> 5) & 3;
        int slab = (fi >> 7) & 1;
        int ks   = (fi >> 8) & 1;
        int gid  = lane >> 2, tig = lane & 3;

        int mrow = slab * 64 + mt * 16 + gid;
        int mb0  = smb[mrow];
        int mb1  = smb[mrow + 8];
        int kb   = ks * 16 + tig * 2;
        int ko0 = skoff[kb],     ko1 = skoff[kb + 1];
        int ko8 = skoff[kb + 8], ko9 = skoff[kb + 9];

        uint4 o;
        o.x = h2(__ldg(x + mb0 + ko0), __ldg(x + mb0 + ko1));
        o.y = h2(__ldg(x + mb1 + ko0), __ldg(x + mb1 + ko1));
        o.z = h2(__ldg(x + mb0 + ko8), __ldg(x + mb0 + ko9));
        o.w = h2(__ldg(x + mb1 + ko8), __ldg(x + mb1 + ko9));
        dst[fi] = o;
    }
}

// ---------------- prep B: weights, fp16, fragment order ----------------
// block = one (chunk c, nblk). 512 fragments (uint2), fragment
// fi = (((ks*2+wn)*4+nt)*32+lane); words b0,b1 of m16n8k16 (col-major B):
//   b0={B[k0][n],B[k0+1][n]} b1={B[k0+8][n],B[k0+9][n]}
//   n = nblk*64 + wn*32 + nt*8 + gid, k0 = ks*16 + 2*tig (within chunk)
__global__ void prep_b_kernel(const float* __restrict__ w) {
    const int c    = blockIdx.x;
    const int nblk = blockIdx.y;
    const int t    = threadIdx.x;

    uint2* dst = reinterpret_cast<uint2*>(g_bh + (size_t)(c * NBLKS + nblk) * 256);
    #pragma unroll
    for (int fi = t; fi < 512; fi += NTHREADS) {
        int lane = fi & 31;
        int nt   = (fi >> 5) & 3;
        int wn   = (fi >> 7) & 1;
        int ks   = (fi >> 8) & 1;
        int gid  = lane >> 2, tig = lane & 3;

        int n = nblk * BN + wn * 32 + nt * 8 + gid;
        int k = c * BK + ks * 16 + tig * 2;
        const float* wp = w + (size_t)k * N_TOTAL + n;
        uint2 o;
        o.x = h2(wp[0],            wp[N_TOTAL]);
        o.y = h2(wp[8 * N_TOTAL],  wp[9 * N_TOTAL]);
        dst[fi] = o;
    }
}

// ---------------- main streaming fp16 GEMM ----------------
__global__ __launch_bounds__(NTHREADS, 4)
void masked_conv_main(float* __restrict__ out)
{
    extern __shared__ char smem[];
    const uint32_t sb = smem_u32(smem);
    const int t  = threadIdx.x;
    const int bn = blockIdx.x;   // fast dim -> A tile reused in L2 across bn
    const int bm = blockIdx.y;

    const int lane   = t & 31;
    const int wid    = t >> 5;
    const int warp_m = wid & 1;     // 2 x 64-row slabs
    const int warp_n = wid >> 1;    // 2 x 32-col slabs
    const int gid    = lane >> 2;
    const int tig    = lane & 3;

    float acc[4][4][4];
    #pragma unroll
    for (int a = 0; a < 4; a++)
        #pragma unroll
        for (int b = 0; b < 4; b++)
            #pragma unroll
            for (int c = 0; c < 4; c++)
                acc[a][b][c] = 0.0f;

    auto load_stage = [&](int chunk, int stg) {
        const uint4* asrc = g_ah + (size_t)(chunk * MTILES + bm) * 512 + t;
        uint32_t ad = sb + stg * STG_BYTES + t * 16;
        #pragma unroll
        for (int j = 0; j < 4; j++)
            cp16(ad + j * 2048, asrc + j * 128);
        const uint4* bsrc = g_bh + (size_t)(chunk * NBLKS + bn) * 256 + t;
        uint32_t bd = ad + STAGE_A_BYTES;
        cp16(bd, bsrc);
        cp16(bd + 2048, bsrc + 128);
    };

    #pragma unroll
    for (int s = 0; s < STAGES - 1; s++) {
        load_stage(s, s);
        asm volatile("cp.async.commit_group;" ::: "memory");
    }

    #pragma unroll 1
    for (int c = 0; c < NCHUNK; c++) {
        const int stg = c & (STAGES - 1);
        int pc = c + STAGES - 1;
        if (pc < NCHUNK) load_stage(pc, pc & (STAGES - 1));
        asm volatile("cp.async.commit_group;" ::: "memory");
        asm volatile("cp.async.wait_group %0;" :: "n"(STAGES - 1) : "memory");
        __syncthreads();

        const uint32_t As = sb + stg * STG_BYTES;
        const uint32_t Bs = As + STAGE_A_BYTES;

        #pragma unroll
        for (int ks = 0; ks < 2; ks++) {
            uint32_t afrag[4][4];
            uint32_t bfrag[4][2];
            #pragma unroll
            for (int mt = 0; mt < 4; mt++) {
                uint32_t addr = As + ((((ks * 2 + warp_m) * 4 + mt) * 32 + lane) << 4);
                asm volatile("ld.shared.v4.b32 {%0,%1,%2,%3}, [%4];"
                             : "=r"(afrag[mt][0]), "=r"(afrag[mt][1]),
                               "=r"(afrag[mt][2]), "=r"(afrag[mt][3])
                             : "r"(addr));
            }
            #pragma unroll
            for (int nt = 0; nt < 4; nt++) {
                uint32_t addr = Bs + ((((ks * 2 + warp_n) * 4 + nt) * 32 + lane) << 3);
                asm volatile("ld.shared.v2.b32 {%0,%1}, [%2];"
                             : "=r"(bfrag[nt][0]), "=r"(bfrag[nt][1])
                             : "r"(addr));
            }
            #pragma unroll
            for (int mt = 0; mt < 4; mt++)
                #pragma unroll
                for (int nt = 0; nt < 4; nt++) {
                    asm volatile(
                        "mma.sync.aligned.m16n8k16.row.col.f32.f16.f16.f32 "
                        "{%0,%1,%2,%3}, {%4,%5,%6,%7}, {%8,%9}, {%0,%1,%2,%3};\n"
                        : "+f"(acc[mt][nt][0]), "+f"(acc[mt][nt][1]),
                          "+f"(acc[mt][nt][2]), "+f"(acc[mt][nt][3])
                        : "r"(afrag[mt][0]), "r"(afrag[mt][1]),
                          "r"(afrag[mt][2]), "r"(afrag[mt][3]),
                          "r"(bfrag[nt][0]), "r"(bfrag[nt][1]));
                }
        }
        __syncthreads();
    }

    // ---- epilogue ----
    #pragma unroll
    for (int mt = 0; mt < 4; mt++) {
        int m0 = bm * BM + warp_m * 64 + mt * 16 + gid;
        int m1 = m0 + 8;
        int nb0 = m0 / OHW, p0 = m0 - nb0 * OHW;
        int nb1 = m1 / OHW, p1 = m1 - nb1 * OHW;
        int base0 = nb0 * OSTRIDE_N + p0;
        int base1 = nb1 * OSTRIDE_N + p1;
        #pragma unroll
        for (int nt = 0; nt < 4; nt++) {
            int oc = bn * BN + warp_n * 32 + nt * 8 + tig * 2;
            if (m0 < M_TOTAL) {
                out[base0 + oc * OHW]       = acc[mt][nt][0];
                out[base0 + (oc + 1) * OHW] = acc[mt][nt][1];
            }
            if (m1 < M_TOTAL) {
                out[base1 + oc * OHW]       = acc[mt][nt][2];
                out[base1 + (oc + 1) * OHW] = acc[mt][nt][3];
            }
        }
    }
}

// ---------------- launch ----------------
extern "C" void kernel_launch(void* const* d_in, const int* in_sizes, int n_in,
                              void* d_out, int out_size) {
    const float* x   = (const float*)d_in[0];   // (16,256,32,32) fp32
    const float* w   = (const float*)d_in[1];   // (1152,512) fp32
    const int*   idx = (const int*)d_in[2];     // (1152,) int32 sorted
    float*       out = (float*)d_out;           // (16,512,30,30) fp32

    prep_a_kernel<<<dim3(NCHUNK, MTILES), 256>>>(x, idx);
    prep_b_kernel<<<dim3(NCHUNK, NBLKS), NTHREADS>>>(w);

    cudaFuncSetAttribute(masked_conv_main,
                         cudaFuncAttributeMaxDynamicSharedMemorySize, SM_TOTAL);
    dim3 grid(NBLKS, MTILES);                   // (8, 113) = 904 CTAs
    masked_conv_main<<<grid, NTHREADS, SM_TOTAL>>>(out);
}

// round 9
// speedup vs baseline: 1.1619x; 1.1619x over previous
#include <cuda_runtime.h>
#include <cuda_fp16.h>
#include <cstdint>

// ---------------- problem constants ----------------
#define M_TOTAL   14400      // 16 * 30 * 30
#define N_TOTAL   512
#define K_TOTAL   1152
#define OHW       900        // 30*30
#define XSTRIDE_N 262144     // 256*32*32
#define OSTRIDE_N 460800     // 512*900

#define BM 128
#define BN 128
#define BK 32
#define NCHUNK   36          // K_TOTAL / BK
#define NITER    18          // 2 chunks per pipeline stage
#define MTILES   113         // ceil(14400/128)
#define NTHREADS 256
#define STAGES   3

// fp16 fragment-ordered tiles per chunk:
//   A (chunk,bm): 128x32 half = 8 KB = 512 uint4
//   B (chunk,bn): 32x128 half = 8 KB = 512 uint4
// One stage = 2 chunks: A 16 KB + B 16 KB
#define STAGE_A_BYTES 16384
#define STG_BYTES     32768
#define SM_TOTAL      (STAGES * STG_BYTES)    // 98304 B -> 2 CTAs/SM

__device__ uint4 g_ah[NCHUNK * MTILES * 512];   // ~33.3 MB
__device__ uint4 g_bh[NCHUNK * 4 * 512];        // ~1.2 MB

// ---------------- helpers ----------------
__device__ __forceinline__ uint32_t smem_u32(const void* p) {
    uint32_t a;
    asm("{ .reg .u64 t; cvta.to.shared.u64 t, %1; cvt.u32.u64 %0, t; }"
        : "=r"(a) : "l"(p));
    return a;
}
__device__ __forceinline__ void cp16(uint32_t dst, const void* src) {
    asm volatile("cp.async.cg.shared.global [%0], [%1], 16;"
                 :: "r"(dst), "l"(src) : "memory");
}
// pack two floats into f16x2 word: lo = a, hi = b
__device__ __forceinline__ uint32_t h2(float a, float b) {
    uint32_t r;
    asm("cvt.rn.f16x2.f32 %0, %1, %2;" : "=r"(r) : "f"(b), "f"(a));
    return r;
}

// ---------------- prep A: gathered im2col, fp16, fragment order ----------------
// block = one (chunk c, mtile bmt). Tile = 512 fragments (uint4), fragment
// fi = (((ks*2+slab)*4+mt)*32+lane); words a0..a3 of m16n8k16:
//   a0={A[m0][k0],A[m0][k0+1]} a1={A[m1][..]} a2={A[m0][k0+8],[k0+9]} a3={A[m1][..]}
//   m0 = slab*64+mt*16+gid, m1 = m0+8, k0 = ks*16 + 2*tig (within chunk)
__global__ void prep_a_kernel(const float* __restrict__ x,
                              const int*   __restrict__ idx) {
    __shared__ int skoff[BK];
    __shared__ int smb[BM];
    const int c   = blockIdx.x;
    const int bmt = blockIdx.y;
    const int t   = threadIdx.x;

    if (t < BK) {
        int v  = idx[c * BK + t];
        int ch = v / 9;
        int rs = v - ch * 9;
        skoff[t] = ch * 1024 + (rs / 3) * 32 + (rs % 3);
    }
    if (t < BM) {
        int m = bmt * BM + t;
        if (m >= M_TOTAL) m = 0;
        int nb  = m / OHW;
        int rem = m - nb * OHW;
        smb[t] = nb * XSTRIDE_N + (rem / 30) * 32 + (rem % 30);
    }
    __syncthreads();

    uint4* dst = g_ah + (size_t)(c * MTILES + bmt) * 512;
    #pragma unroll
    for (int fi = t; fi < 512; fi += NTHREADS) {
        int lane = fi & 31;
        int mt   = (fi >> 5) & 3;
        int slab = (fi >> 7) & 1;
        int ks   = (fi >> 8) & 1;
        int gid  = lane >> 2, tig = lane & 3;

        int mrow = slab * 64 + mt * 16 + gid;
        int mb0  = smb[mrow];
        int mb1  = smb[mrow + 8];
        int kb   = ks * 16 + tig * 2;
        int ko0 = skoff[kb],     ko1 = skoff[kb + 1];
        int ko8 = skoff[kb + 8], ko9 = skoff[kb + 9];

        uint4 o;
        o.x = h2(__ldg(x + mb0 + ko0), __ldg(x + mb0 + ko1));
        o.y = h2(__ldg(x + mb1 + ko0), __ldg(x + mb1 + ko1));
        o.z = h2(__ldg(x + mb0 + ko8), __ldg(x + mb0 + ko9));
        o.w = h2(__ldg(x + mb1 + ko8), __ldg(x + mb1 + ko9));
        dst[fi] = o;
    }
}

// ---------------- prep B: weights, fp16, fragment order ----------------
// block = one (chunk c, nblk of 4). 1024 fragments (uint2), fragment
// fi = (((ks*4+wn)*4+nt)*32+lane); words b0,b1 of m16n8k16 (col-major B):
//   b0={B[k0][n],B[k0+1][n]} b1={B[k0+8][n],B[k0+9][n]}
//   n = nblk*128 + wn*32 + nt*8 + gid, k0 = ks*16 + 2*tig (within chunk)
__global__ void prep_b_kernel(const float* __restrict__ w) {
    const int c    = blockIdx.x;
    const int nblk = blockIdx.y;
    const int t    = threadIdx.x;

    uint2* dst = reinterpret_cast<uint2*>(g_bh + (size_t)(c * 4 + nblk) * 512);
    #pragma unroll
    for (int fi = t; fi < 1024; fi += NTHREADS) {
        int lane = fi & 31;
        int nt   = (fi >> 5) & 3;
        int wn   = (fi >> 7) & 3;
        int ks   = (fi >> 9) & 1;
        int gid  = lane >> 2, tig = lane & 3;

        int n = nblk * BN + wn * 32 + nt * 8 + gid;
        int k = c * BK + ks * 16 + tig * 2;
        const float* wp = w + (size_t)k * N_TOTAL + n;
        uint2 o;
        o.x = h2(wp[0],            wp[N_TOTAL]);
        o.y = h2(wp[8 * N_TOTAL],  wp[9 * N_TOTAL]);
        dst[fi] = o;
    }
}

// ---------------- main streaming fp16 GEMM ----------------
__global__ __launch_bounds__(NTHREADS, 2)
void masked_conv_main(float* __restrict__ out)
{
    extern __shared__ char smem[];
    const uint32_t sb = smem_u32(smem);
    const int t  = threadIdx.x;
    const int bn = blockIdx.x;   // fast dim -> A tile reused in L2 across bn
    const int bm = blockIdx.y;

    const int lane   = t & 31;
    const int wid    = t >> 5;
    const int warp_m = wid & 1;
    const int warp_n = wid >> 1;
    const int gid    = lane >> 2;
    const int tig    = lane & 3;

    float acc[4][4][4];
    #pragma unroll
    for (int a = 0; a < 4; a++)
        #pragma unroll
        for (int b = 0; b < 4; b++)
            #pragma unroll
            for (int c = 0; c < 4; c++)
                acc[a][b][c] = 0.0f;

    // one stage = 2 chunks
    auto load_stage = [&](int iter, int stg) {
        #pragma unroll
        for (int sub = 0; sub < 2; sub++) {
            int chunk = iter * 2 + sub;
            const uint4* asrc = g_ah + (size_t)(chunk * MTILES + bm) * 512 + t;
            uint32_t ad = sb + stg * STG_BYTES + sub * 8192 + t * 16;
            cp16(ad, asrc);
            cp16(ad + 4096, asrc + 256);
            const uint4* bsrc = g_bh + (size_t)(chunk * 4 + bn) * 512 + t;
            uint32_t bd = ad + STAGE_A_BYTES;
            cp16(bd, bsrc);
            cp16(bd + 4096, bsrc + 256);
        }
    };

    // prologue: stages 0,1
    load_stage(0, 0);
    asm volatile("cp.async.commit_group;" ::: "memory");
    load_stage(1, 1);
    asm volatile("cp.async.commit_group;" ::: "memory");

    int stg = 0;   // stage of current iter
    int pst = 2;   // stage of prefetch target (iter+2)
    #pragma unroll 1
    for (int i = 0; i < NITER; i++) {
        // ensure stage for iter i has landed
        asm volatile("cp.async.wait_group 1;" ::: "memory");
        // all threads done reading the stage about to be overwritten
        __syncthreads();
        if (i + 2 < NITER) load_stage(i + 2, pst);
        asm volatile("cp.async.commit_group;" ::: "memory");

        const uint32_t Sbase = sb + stg * STG_BYTES;
        #pragma unroll
        for (int sub = 0; sub < 2; sub++) {
            const uint32_t As = Sbase + sub * 8192;
            const uint32_t Bs = As + STAGE_A_BYTES;
            #pragma unroll
            for (int ks = 0; ks < 2; ks++) {
                uint32_t afrag[4][4];
                uint32_t bfrag[4][2];
                #pragma unroll
                for (int mt = 0; mt < 4; mt++) {
                    uint32_t addr = As + ((((ks * 2 + warp_m) * 4 + mt) * 32 + lane) << 4);
                    asm volatile("ld.shared.v4.b32 {%0,%1,%2,%3}, [%4];"
                                 : "=r"(afrag[mt][0]), "=r"(afrag[mt][1]),
                                   "=r"(afrag[mt][2]), "=r"(afrag[mt][3])
                                 : "r"(addr));
                }
                #pragma unroll
                for (int nt = 0; nt < 4; nt++) {
                    uint32_t addr = Bs + ((((ks * 4 + warp_n) * 4 + nt) * 32 + lane) << 3);
                    asm volatile("ld.shared.v2.b32 {%0,%1}, [%2];"
                                 : "=r"(bfrag[nt][0]), "=r"(bfrag[nt][1])
                                 : "r"(addr));
                }
                #pragma unroll
                for (int mt = 0; mt < 4; mt++)
                    #pragma unroll
                    for (int nt = 0; nt < 4; nt++) {
                        asm volatile(
                            "mma.sync.aligned.m16n8k16.row.col.f32.f16.f16.f32 "
                            "{%0,%1,%2,%3}, {%4,%5,%6,%7}, {%8,%9}, {%0,%1,%2,%3};\n"
                            : "+f"(acc[mt][nt][0]), "+f"(acc[mt][nt][1]),
                              "+f"(acc[mt][nt][2]), "+f"(acc[mt][nt][3])
                            : "r"(afrag[mt][0]), "r"(afrag[mt][1]),
                              "r"(afrag[mt][2]), "r"(afrag[mt][3]),
                              "r"(bfrag[nt][0]), "r"(bfrag[nt][1]));
                    }
            }
        }

        stg = (stg == STAGES - 1) ? 0 : stg + 1;
        pst = (pst == STAGES - 1) ? 0 : pst + 1;
    }

    // ---- epilogue ----
    #pragma unroll
    for (int mt = 0; mt < 4; mt++) {
        int m0 = bm * BM + warp_m * 64 + mt * 16 + gid;
        int m1 = m0 + 8;
        int nb0 = m0 / OHW, p0 = m0 - nb0 * OHW;
        int nb1 = m1 / OHW, p1 = m1 - nb1 * OHW;
        int base0 = nb0 * OSTRIDE_N + p0;
        int base1 = nb1 * OSTRIDE_N + p1;
        #pragma unroll
        for (int nt = 0; nt < 4; nt++) {
            int oc = bn * BN + warp_n * 32 + nt * 8 + tig * 2;
            if (m0 < M_TOTAL) {
                out[base0 + oc * OHW]       = acc[mt][nt][0];
                out[base0 + (oc + 1) * OHW] = acc[mt][nt][1];
            }
            if (m1 < M_TOTAL) {
                out[base1 + oc * OHW]       = acc[mt][nt][2];
                out[base1 + (oc + 1) * OHW] = acc[mt][nt][3];
            }
        }
    }
}

// ---------------- launch ----------------
extern "C" void kernel_launch(void* const* d_in, const int* in_sizes, int n_in,
                              void* d_out, int out_size) {
    const float* x   = (const float*)d_in[0];   // (16,256,32,32) fp32
    const float* w   = (const float*)d_in[1];   // (1152,512) fp32
    const int*   idx = (const int*)d_in[2];     // (1152,) int32 sorted
    float*       out = (float*)d_out;           // (16,512,30,30) fp32

    prep_a_kernel<<<dim3(NCHUNK, MTILES), NTHREADS>>>(x, idx);
    prep_b_kernel<<<dim3(NCHUNK, 4), NTHREADS>>>(w);

    cudaFuncSetAttribute(masked_conv_main,
                         cudaFuncAttributeMaxDynamicSharedMemorySize, SM_TOTAL);
    dim3 grid(N_TOTAL / BN, MTILES);            // (4, 113)
    masked_conv_main<<<grid, NTHREADS, SM_TOTAL>>>(out);
}

// round 10
// speedup vs baseline: 1.2464x; 1.0727x over previous
#include <cuda_runtime.h>
#include <cuda_fp16.h>
#include <cstdint>

// ---------------- problem constants ----------------
#define M_TOTAL   14400      // 16 * 30 * 30
#define N_TOTAL   512
#define K_TOTAL   1152
#define OHW       900        // 30*30
#define XSTRIDE_N 262144     // 256*32*32
#define OSTRIDE_N 460800     // 512*900

#define BM 128
#define BN 128
#define BK 32
#define NCHUNK   36          // K_TOTAL / BK
#define NSTEPS   72          // 2 ks-steps per chunk
#define MTILES   113         // ceil(14400/128)
#define NTHREADS 256

__device__ uint4 g_ah[NCHUNK * MTILES * 512];   // ~33.3 MB, per-thread A fragments
__device__ uint4 g_bh[NCHUNK * 4 * 512];        // ~1.2 MB,  per-thread B fragments

// pack two floats into f16x2 word: lo = a, hi = b
__device__ __forceinline__ uint32_t h2(float a, float b) {
    uint32_t r;
    asm("cvt.rn.f16x2.f32 %0, %1, %2;" : "=r"(r) : "f"(b), "f"(a));
    return r;
}

// ---------------- prep A: gathered im2col, fp16, fragment order ----------------
// block = one (chunk c, mtile bmt). Tile = 512 fragments (uint4), fragment
// fi = (((ks*2+slab)*4+mt)*32+lane); words a0..a3 of m16n8k16:
//   a0={A[m0][k0],A[m0][k0+1]} a1={A[m1][..]} a2={A[m0][k0+8],[k0+9]} a3={A[m1][..]}
//   m0 = slab*64+mt*16+gid, m1 = m0+8, k0 = ks*16 + 2*tig (within chunk)
__global__ void prep_a_kernel(const float* __restrict__ x,
                              const int*   __restrict__ idx) {
    __shared__ int skoff[BK];
    __shared__ int smb[BM];
    const int c   = blockIdx.x;
    const int bmt = blockIdx.y;
    const int t   = threadIdx.x;

    if (t < BK) {
        int v  = idx[c * BK + t];
        int ch = v / 9;
        int rs = v - ch * 9;
        skoff[t] = ch * 1024 + (rs / 3) * 32 + (rs % 3);
    }
    if (t < BM) {
        int m = bmt * BM + t;
        if (m >= M_TOTAL) m = 0;
        int nb  = m / OHW;
        int rem = m - nb * OHW;
        smb[t] = nb * XSTRIDE_N + (rem / 30) * 32 + (rem % 30);
    }
    __syncthreads();

    uint4* dst = g_ah + (size_t)(c * MTILES + bmt) * 512;
    #pragma unroll
    for (int fi = t; fi < 512; fi += NTHREADS) {
        int lane = fi & 31;
        int mt   = (fi >> 5) & 3;
        int slab = (fi >> 7) & 1;
        int ks   = (fi >> 8) & 1;
        int gid  = lane >> 2, tig = lane & 3;

        int mrow = slab * 64 + mt * 16 + gid;
        int mb0  = smb[mrow];
        int mb1  = smb[mrow + 8];
        int kb   = ks * 16 + tig * 2;
        int ko0 = skoff[kb],     ko1 = skoff[kb + 1];
        int ko8 = skoff[kb + 8], ko9 = skoff[kb + 9];

        uint4 o;
        o.x = h2(__ldg(x + mb0 + ko0), __ldg(x + mb0 + ko1));
        o.y = h2(__ldg(x + mb1 + ko0), __ldg(x + mb1 + ko1));
        o.z = h2(__ldg(x + mb0 + ko8), __ldg(x + mb0 + ko9));
        o.w = h2(__ldg(x + mb1 + ko8), __ldg(x + mb1 + ko9));
        dst[fi] = o;
    }
}

// ---------------- prep B: weights, fp16, fragment order ----------------
// block = one (chunk c, nblk). 1024 uint2 fragments,
// fj = (((ks*4+wn)*4+nt)*32+lane); b0={B[k0][n],B[k0+1][n]} b1={B[k0+8][n],B[k0+9][n]}
//   n = nblk*128 + wn*32 + nt*8 + gid, k0 = ks*16 + 2*tig (within chunk)
__global__ void prep_b_kernel(const float* __restrict__ w) {
    const int c    = blockIdx.x;
    const int nblk = blockIdx.y;
    const int t    = threadIdx.x;

    uint2* dst = reinterpret_cast<uint2*>(g_bh + (size_t)(c * 4 + nblk) * 512);
    #pragma unroll
    for (int fi = t; fi < 1024; fi += NTHREADS) {
        int lane = fi & 31;
        int nt   = (fi >> 5) & 3;
        int wn   = (fi >> 7) & 3;
        int ks   = (fi >> 9) & 1;
        int gid  = lane >> 2, tig = lane & 3;

        int n = nblk * BN + wn * 32 + nt * 8 + gid;
        int k = c * BK + ks * 16 + tig * 2;
        const float* wp = w + (size_t)k * N_TOTAL + n;
        uint2 o;
        o.x = h2(wp[0],            wp[N_TOTAL]);
        o.y = h2(wp[8 * N_TOTAL],  wp[9 * N_TOTAL]);
        dst[fi] = o;
    }
}

// ---------------- main: sync-free register-streamed fp16 GEMM ----------------
__global__ __launch_bounds__(NTHREADS, 2)
void masked_conv_main(float* __restrict__ out)
{
    const int t  = threadIdx.x;
    const int bn = blockIdx.x;   // fast dim -> A hot in L2 across bn
    const int bm = blockIdx.y;

    const int lane   = t & 31;
    const int wid    = t >> 5;
    const int warp_m = wid & 1;
    const int warp_n = wid >> 1;
    const int gid    = lane >> 2;
    const int tig    = lane & 3;

    float acc[4][4][4];
    #pragma unroll
    for (int a = 0; a < 4; a++)
        #pragma unroll
        for (int b = 0; b < 4; b++)
            #pragma unroll
            for (int c = 0; c < 4; c++)
                acc[a][b][c] = 0.0f;

    // per-thread fragment base pointers (ks term added per step)
    const uint4* pa0 = g_ah + (size_t)bm * 512 + (warp_m * 4) * 32 + lane;
    const uint2* pb0 = reinterpret_cast<const uint2*>(g_bh + (size_t)bn * 512)
                       + (warp_n * 4) * 32 + lane;

    uint4 Af[2][4];
    uint2 Bf[2][4];

    auto load_step = [&](int s, int buf) {
        int c  = s >> 1;
        int ks = s & 1;
        const uint4* pa = pa0 + (size_t)c * (MTILES * 512) + ks * 256;
        #pragma unroll
        for (int mt = 0; mt < 4; mt++)
            Af[buf][mt] = __ldg(pa + mt * 32);
        const uint2* pb = pb0 + (size_t)c * (4 * 1024) + ks * 512;
        #pragma unroll
        for (int nt = 0; nt < 4; nt++)
            Bf[buf][nt] = __ldg(pb + nt * 32);
    };

    auto compute = [&](int buf) {
        #pragma unroll
        for (int mt = 0; mt < 4; mt++)
            #pragma unroll
            for (int nt = 0; nt < 4; nt++) {
                asm volatile(
                    "mma.sync.aligned.m16n8k16.row.col.f32.f16.f16.f32 "
                    "{%0,%1,%2,%3}, {%4,%5,%6,%7}, {%8,%9}, {%0,%1,%2,%3};\n"
                    : "+f"(acc[mt][nt][0]), "+f"(acc[mt][nt][1]),
                      "+f"(acc[mt][nt][2]), "+f"(acc[mt][nt][3])
                    : "r"(Af[buf][mt].x), "r"(Af[buf][mt].y),
                      "r"(Af[buf][mt].z), "r"(Af[buf][mt].w),
                      "r"(Bf[buf][nt].x), "r"(Bf[buf][nt].y));
            }
    };

    load_step(0, 0);
    #pragma unroll 1
    for (int s = 0; s < NSTEPS; s += 2) {
        load_step(s + 1, 1);
        compute(0);
        if (s + 2 < NSTEPS) load_step(s + 2, 0);
        compute(1);
    }

    // ---- epilogue ----
    #pragma unroll
    for (int mt = 0; mt < 4; mt++) {
        int m0 = bm * BM + warp_m * 64 + mt * 16 + gid;
        int m1 = m0 + 8;
        int nb0 = m0 / OHW, p0 = m0 - nb0 * OHW;
        int nb1 = m1 / OHW, p1 = m1 - nb1 * OHW;
        int base0 = nb0 * OSTRIDE_N + p0;
        int base1 = nb1 * OSTRIDE_N + p1;
        #pragma unroll
        for (int nt = 0; nt < 4; nt++) {
            int oc = bn * BN + warp_n * 32 + nt * 8 + tig * 2;
            if (m0 < M_TOTAL) {
                out[base0 + oc * OHW]       = acc[mt][nt][0];
                out[base0 + (oc + 1) * OHW] = acc[mt][nt][1];
            }
            if (m1 < M_TOTAL) {
                out[base1 + oc * OHW]       = acc[mt][nt][2];
                out[base1 + (oc + 1) * OHW] = acc[mt][nt][3];
            }
        }
    }
}

// ---------------- launch ----------------
extern "C" void kernel_launch(void* const* d_in, const int* in_sizes, int n_in,
                              void* d_out, int out_size) {
    const float* x   = (const float*)d_in[0];   // (16,256,32,32) fp32
    const float* w   = (const float*)d_in[1];   // (1152,512) fp32
    const int*   idx = (const int*)d_in[2];     // (1152,) int32 sorted
    float*       out = (float*)d_out;           // (16,512,30,30) fp32

    prep_a_kernel<<<dim3(NCHUNK, MTILES), NTHREADS>>>(x, idx);
    prep_b_kernel<<<dim3(NCHUNK, 4), NTHREADS>>>(w);

    dim3 grid(N_TOTAL / BN, MTILES);            // (4, 113)
    masked_conv_main<<<grid, NTHREADS>>>(out);
}

// round 11
// speedup vs baseline: 1.3873x; 1.1130x over previous
#include <cuda_runtime.h>
#include <cuda_fp16.h>
#include <cstdint>

// ---------------- problem constants ----------------
#define M_TOTAL   14400      // 16 * 30 * 30
#define N_TOTAL   512
#define K_TOTAL   1152
#define OHW       900        // 30*30
#define XSTRIDE_N 262144     // 256*32*32
#define OSTRIDE_N 460800     // 512*900

#define BM 128
#define BN 64
#define BK 32
#define NCHUNK   36          // K_TOTAL / BK
#define NSTEPS   72          // 2 ks-steps per chunk
#define MTILES   113         // ceil(14400/128)
#define NBLKS    8           // N_TOTAL / BN
#define PTHREADS 256
#define NTHREADS 128

__device__ uint4 g_ah[NCHUNK * MTILES * 512];   // ~33.3 MB, per-thread A fragments
__device__ uint4 g_bh[NCHUNK * NBLKS * 256];    // ~1.2 MB,  per-thread B fragments

// pack two floats into f16x2 word: lo = a, hi = b
__device__ __forceinline__ uint32_t h2(float a, float b) {
    uint32_t r;
    asm("cvt.rn.f16x2.f32 %0, %1, %2;" : "=r"(r) : "f"(b), "f"(a));
    return r;
}

// ---------------- fused prep: A gather (by<113) or B pack (by>=113) ----------------
// A tile (chunk c, mtile bmt): 512 uint4 fragments,
//   fi = (((ks*2+slab)*4+mt)*32+lane); a0..a3 of m16n8k16:
//   a0={A[m0][k0],A[m0][k0+1]} a1={A[m1][..]} a2={A[m0][k0+8],[k0+9]} a3={A[m1][..]}
//   m0 = slab*64+mt*16+gid, m1 = m0+8, k0 = ks*16 + 2*tig (within chunk)
// B tile (chunk c, nblk): 512 uint2 fragments,
//   fj = (((ks*2+wn)*4+nt)*32+lane); b0={B[k0][n],B[k0+1][n]} b1={B[k0+8][n],B[k0+9][n]}
//   n = nblk*64 + wn*32 + nt*8 + gid, k0 = ks*16 + 2*tig (within chunk)
__global__ void prep_kernel(const float* __restrict__ x,
                            const float* __restrict__ w,
                            const int*   __restrict__ idx) {
    const int c  = blockIdx.x;
    const int by = blockIdx.y;
    const int t  = threadIdx.x;

    if (by >= MTILES) {
        // ---- B pack ----
        const int nblk = by - MTILES;
        uint2* dst = reinterpret_cast<uint2*>(g_bh + (size_t)(c * NBLKS + nblk) * 256);
        #pragma unroll
        for (int fi = t; fi < 512; fi += PTHREADS) {
            int lane = fi & 31;
            int nt   = (fi >> 5) & 3;
            int wn   = (fi >> 7) & 1;
            int ks   = (fi >> 8) & 1;
            int gid  = lane >> 2, tig = lane & 3;

            int n = nblk * BN + wn * 32 + nt * 8 + gid;
            int k = c * BK + ks * 16 + tig * 2;
            const float* wp = w + (size_t)k * N_TOTAL + n;
            uint2 o;
            o.x = h2(wp[0],           wp[N_TOTAL]);
            o.y = h2(wp[8 * N_TOTAL], wp[9 * N_TOTAL]);
            dst[fi] = o;
        }
        return;
    }

    // ---- A gather ----
    __shared__ int skoff[BK];
    __shared__ int smb[BM];
    const int bmt = by;

    if (t < BK) {
        int v  = idx[c * BK + t];
        int ch = v / 9;
        int rs = v - ch * 9;
        skoff[t] = ch * 1024 + (rs / 3) * 32 + (rs % 3);
    }
    if (t < BM) {
        int m = bmt * BM + t;
        if (m >= M_TOTAL) m = 0;
        int nb  = m / OHW;
        int rem = m - nb * OHW;
        smb[t] = nb * XSTRIDE_N + (rem / 30) * 32 + (rem % 30);
    }
    __syncthreads();

    uint4* dst = g_ah + (size_t)(c * MTILES + bmt) * 512;
    #pragma unroll
    for (int fi = t; fi < 512; fi += PTHREADS) {
        int lane = fi & 31;
        int mt   = (fi >> 5) & 3;
        int slab = (fi >> 7) & 1;
        int ks   = (fi >> 8) & 1;
        int gid  = lane >> 2, tig = lane & 3;

        int mrow = slab * 64 + mt * 16 + gid;
        int mb0  = smb[mrow];
        int mb1  = smb[mrow + 8];
        int kb   = ks * 16 + tig * 2;
        int ko0 = skoff[kb],     ko1 = skoff[kb + 1];
        int ko8 = skoff[kb + 8], ko9 = skoff[kb + 9];

        uint4 o;
        o.x = h2(__ldg(x + mb0 + ko0), __ldg(x + mb0 + ko1));
        o.y = h2(__ldg(x + mb1 + ko0), __ldg(x + mb1 + ko1));
        o.z = h2(__ldg(x + mb0 + ko8), __ldg(x + mb0 + ko9));
        o.w = h2(__ldg(x + mb1 + ko8), __ldg(x + mb1 + ko9));
        dst[fi] = o;
    }
}

// ---------------- main: sync-free register-streamed fp16 GEMM ----------------
__global__ __launch_bounds__(NTHREADS, 4)
void masked_conv_main(float* __restrict__ out)
{
    const int t  = threadIdx.x;
    const int bn = blockIdx.x;   // fast dim -> A hot in L1/L2 across bn
    const int bm = blockIdx.y;

    const int lane   = t & 31;
    const int wid    = t >> 5;
    const int warp_m = wid & 1;     // 2 x 64-row slabs
    const int warp_n = wid >> 1;    // 2 x 32-col slabs
    const int gid    = lane >> 2;
    const int tig    = lane & 3;

    float acc[4][4][4];
    #pragma unroll
    for (int a = 0; a < 4; a++)
        #pragma unroll
        for (int b = 0; b < 4; b++)
            #pragma unroll
            for (int c = 0; c < 4; c++)
                acc[a][b][c] = 0.0f;

    // per-thread fragment base pointers
    const uint4* pa0 = g_ah + (size_t)bm * 512 + (warp_m * 4) * 32 + lane;
    const uint2* pb0 = reinterpret_cast<const uint2*>(g_bh)
                       + (size_t)bn * 512 + warp_n * 128 + lane;

    uint4 Af[2][4];
    uint2 Bf[2][4];

    auto load_step = [&](int s, int buf) {
        int c  = s >> 1;
        int ks = s & 1;
        const uint4* pa = pa0 + (size_t)c * (MTILES * 512) + ks * 256;
        #pragma unroll
        for (int mt = 0; mt < 4; mt++)
            Af[buf][mt] = __ldg(pa + mt * 32);
        const uint2* pb = pb0 + (size_t)c * (NBLKS * 512) + ks * 256;
        #pragma unroll
        for (int nt = 0; nt < 4; nt++)
            Bf[buf][nt] = __ldg(pb + nt * 32);
    };

    auto compute = [&](int buf) {
        #pragma unroll
        for (int mt = 0; mt < 4; mt++)
            #pragma unroll
            for (int nt = 0; nt < 4; nt++) {
                asm volatile(
                    "mma.sync.aligned.m16n8k16.row.col.f32.f16.f16.f32 "
                    "{%0,%1,%2,%3}, {%4,%5,%6,%7}, {%8,%9}, {%0,%1,%2,%3};\n"
                    : "+f"(acc[mt][nt][0]), "+f"(acc[mt][nt][1]),
                      "+f"(acc[mt][nt][2]), "+f"(acc[mt][nt][3])
                    : "r"(Af[buf][mt].x), "r"(Af[buf][mt].y),
                      "r"(Af[buf][mt].z), "r"(Af[buf][mt].w),
                      "r"(Bf[buf][nt].x), "r"(Bf[buf][nt].y));
            }
    };

    load_step(0, 0);
    #pragma unroll 1
    for (int s = 0; s < NSTEPS; s += 2) {
        load_step(s + 1, 1);
        compute(0);
        if (s + 2 < NSTEPS) load_step(s + 2, 0);
        compute(1);
    }

    // ---- epilogue ----
    #pragma unroll
    for (int mt = 0; mt < 4; mt++) {
        int m0 = bm * BM + warp_m * 64 + mt * 16 + gid;
        int m1 = m0 + 8;
        int nb0 = m0 / OHW, p0 = m0 - nb0 * OHW;
        int nb1 = m1 / OHW, p1 = m1 - nb1 * OHW;
        int base0 = nb0 * OSTRIDE_N + p0;
        int base1 = nb1 * OSTRIDE_N + p1;
        #pragma unroll
        for (int nt = 0; nt < 4; nt++) {
            int oc = bn * BN + warp_n * 32 + nt * 8 + tig * 2;
            if (m0 < M_TOTAL) {
                out[base0 + oc * OHW]       = acc[mt][nt][0];
                out[base0 + (oc + 1) * OHW] = acc[mt][nt][1];
            }
            if (m1 < M_TOTAL) {
                out[base1 + oc * OHW]       = acc[mt][nt][2];
                out[base1 + (oc + 1) * OHW] = acc[mt][nt][3];
            }
        }
    }
}

// ---------------- launch ----------------
extern "C" void kernel_launch(void* const* d_in, const int* in_sizes, int n_in,
                              void* d_out, int out_size) {
    const float* x   = (const float*)d_in[0];   // (16,256,32,32) fp32
    const float* w   = (const float*)d_in[1];   // (1152,512) fp32
    const int*   idx = (const int*)d_in[2];     // (1152,) int32 sorted
    float*       out = (float*)d_out;           // (16,512,30,30) fp32

    prep_kernel<<<dim3(NCHUNK, MTILES + NBLKS), PTHREADS>>>(x, w, idx);

    dim3 grid(NBLKS, MTILES);                   // (8, 113) = 904 CTAs
    masked_conv_main<<<grid, NTHREADS>>>(out);
}